// round 2
// baseline (speedup 1.0000x reference)
#include <cuda_runtime.h>
#include <cuda_fp16.h>
#include <cstdint>

// BMM_S8T_S8N_F16T: out[b,m,n] = f32( fp16_round( alpha * sum_k a[b,m,k]*b[b,n,k] ) )
// a: (64,1024,128) int32 (values 0..126), b: (64,1024,128) int32, alpha: (1,) f32
// Output buffer is float32 (values rounded through fp16 to match reference).

#define BATCH 64
#define MDIM 1024
#define NDIM 1024
#define KDIM 128

#define BM 128
#define BN 128
#define ROWSTRIDE 36       // 32 k-words + 4 pad words (16B) -> conflict-free banks

__global__ __launch_bounds__(256, 2)
void bmm_s8_imma_kernel(const int* __restrict__ A,
                        const int* __restrict__ Bmat,
                        const float* __restrict__ alpha_p,
                        float* __restrict__ Out) {
    __shared__ uint32_t As[BM * ROWSTRIDE];
    __shared__ uint32_t Bs[BN * ROWSTRIDE];

    const int tid  = threadIdx.x;
    const int lane = tid & 31;
    const int warp = tid >> 5;

    const int bn = blockIdx.x;   // N block (8)
    const int bm = blockIdx.y;   // M block (8)
    const int bz = blockIdx.z;   // batch (64)

    const int* Abase = A    + ((size_t)bz * MDIM + (size_t)bm * BM) * KDIM;
    const int* Bbase = Bmat + ((size_t)bz * NDIM + (size_t)bn * BN) * KDIM;

    // ---- Load int32 tiles, pack to s8x4, stage in smem ----
    #pragma unroll
    for (int i = 0; i < 16; i++) {
        int idx = tid + i * 256;
        int row = idx >> 5;          // 0..127
        int col = idx & 31;          // 0..31 (word within row)
        int4 va = *(const int4*)(Abase + row * KDIM + col * 4);
        uint32_t pa = (uint32_t)(va.x & 0xFF)
                    | ((uint32_t)(va.y & 0xFF) << 8)
                    | ((uint32_t)(va.z & 0xFF) << 16)
                    | ((uint32_t)(va.w & 0xFF) << 24);
        As[row * ROWSTRIDE + col] = pa;

        int4 vb = *(const int4*)(Bbase + row * KDIM + col * 4);
        uint32_t pb = (uint32_t)(vb.x & 0xFF)
                    | ((uint32_t)(vb.y & 0xFF) << 8)
                    | ((uint32_t)(vb.z & 0xFF) << 16)
                    | ((uint32_t)(vb.w & 0xFF) << 24);
        Bs[row * ROWSTRIDE + col] = pb;
    }
    __syncthreads();

    // ---- Warp tiling: 2 x 4 warps, each warp 64(M) x 32(N) ----
    const int warp_m = warp & 1;
    const int warp_n = warp >> 1;

    int acc[4][4][4];
    #pragma unroll
    for (int mi = 0; mi < 4; mi++)
        #pragma unroll
        for (int ni = 0; ni < 4; ni++)
            #pragma unroll
            for (int r = 0; r < 4; r++)
                acc[mi][ni][r] = 0;

    const int lq = lane >> 2;   // group id (0..7)
    const int lr = lane & 3;    // thread-in-group (0..3)

    #pragma unroll
    for (int ks = 0; ks < 4; ks++) {         // 4 k-steps of 32
        uint32_t af[4][4];
        #pragma unroll
        for (int mi = 0; mi < 4; mi++) {
            int r = warp_m * 64 + mi * 16 + lq;
            const uint32_t* p  = &As[r * ROWSTRIDE + ks * 8 + lr];
            af[mi][0] = p[0];                     // (row g,   k 0..15)
            af[mi][2] = p[4];                     // (row g,   k 16..31)
            const uint32_t* p8 = p + 8 * ROWSTRIDE;
            af[mi][1] = p8[0];                    // (row g+8, k 0..15)
            af[mi][3] = p8[4];                    // (row g+8, k 16..31)
        }
        uint32_t bf[4][2];
        #pragma unroll
        for (int ni = 0; ni < 4; ni++) {
            int c = warp_n * 32 + ni * 8 + lq;
            const uint32_t* p = &Bs[c * ROWSTRIDE + ks * 8 + lr];
            bf[ni][0] = p[0];
            bf[ni][1] = p[4];
        }
        #pragma unroll
        for (int mi = 0; mi < 4; mi++) {
            #pragma unroll
            for (int ni = 0; ni < 4; ni++) {
                asm volatile(
                    "mma.sync.aligned.m16n8k32.row.col.s32.s8.s8.s32 "
                    "{%0,%1,%2,%3}, {%4,%5,%6,%7}, {%8,%9}, {%0,%1,%2,%3};"
                    : "+r"(acc[mi][ni][0]), "+r"(acc[mi][ni][1]),
                      "+r"(acc[mi][ni][2]), "+r"(acc[mi][ni][3])
                    : "r"(af[mi][0]), "r"(af[mi][1]), "r"(af[mi][2]), "r"(af[mi][3]),
                      "r"(bf[ni][0]), "r"(bf[ni][1]));
            }
        }
    }

    // ---- Epilogue: round(alpha * acc) through fp16, store as f32 ----
    const float alpha = *alpha_p;
    float* obase = Out + ((size_t)bz * MDIM + (size_t)bm * BM) * NDIM + (size_t)bn * BN;

    #pragma unroll
    for (int mi = 0; mi < 4; mi++) {
        #pragma unroll
        for (int ni = 0; ni < 4; ni++) {
            int r0 = warp_m * 64 + mi * 16 + lq;
            int c0 = warp_n * 32 + ni * 8 + lr * 2;
            float2 v0;
            v0.x = __half2float(__float2half_rn(alpha * (float)acc[mi][ni][0]));
            v0.y = __half2float(__float2half_rn(alpha * (float)acc[mi][ni][1]));
            *(float2*)(obase + (size_t)r0 * NDIM + c0) = v0;
            float2 v1;
            v1.x = __half2float(__float2half_rn(alpha * (float)acc[mi][ni][2]));
            v1.y = __half2float(__float2half_rn(alpha * (float)acc[mi][ni][3]));
            *(float2*)(obase + (size_t)(r0 + 8) * NDIM + c0) = v1;
        }
    }
}

extern "C" void kernel_launch(void* const* d_in, const int* in_sizes, int n_in,
                              void* d_out, int out_size) {
    // Robust input selection: alpha is the size-1 input; the two large tensors
    // are a then b in index order (holds for both dict order and alphabetical).
    int ai = -1, bi = -1, si = -1;
    for (int i = 0; i < n_in; i++) {
        if (in_sizes[i] == 1) { si = i; }
        else if (ai < 0)      { ai = i; }
        else                  { bi = i; }
    }
    const int*   a     = (const int*)d_in[ai];
    const int*   b     = (const int*)d_in[bi];
    const float* alpha = (const float*)d_in[si];
    float*       out   = (float*)d_out;

    dim3 grid(NDIM / BN, MDIM / BM, BATCH);   // (8, 8, 64)
    dim3 block(256);
    bmm_s8_imma_kernel<<<grid, block>>>(a, b, alpha, out);
}

// round 4
// speedup vs baseline: 1.1075x; 1.1075x over previous
#include <cuda_runtime.h>
#include <cuda_fp16.h>
#include <cstdint>

// BMM_S8T_S8N_F16T hybrid: legacy IMMA (k 0..95) + dp4a on ALU pipe (k 96..127),
// accumulating into the same per-thread fragment registers.
// out[b,m,n] = f32( fp16_round( alpha * sum_k a[b,m,k]*b[b,n,k] ) )
// a: (64,1024,128) int32 (0..126), b: (64,1024,128) int32, alpha: (1,) f32

#define BATCH 64
#define MDIM 1024
#define NDIM 1024
#define KDIM 128

#define BM 128
#define BN 128
#define ROWSTRIDE 36       // 32 k-words + 4 pad words -> conflict-free banks

#define K_MMA_STEPS 3      // IMMA covers k-words 0..23 (k 0..95)
#define KW_DP4A 24         // dp4a covers k-words 24..31 (k 96..127)

__global__ __launch_bounds__(256, 2)
void bmm_s8_hybrid_kernel(const int* __restrict__ A,
                          const int* __restrict__ Bmat,
                          const float* __restrict__ alpha_p,
                          float* __restrict__ Out) {
    __shared__ uint32_t As[BM * ROWSTRIDE];
    __shared__ uint32_t Bs[BN * ROWSTRIDE];

    const int tid  = threadIdx.x;
    const int lane = tid & 31;
    const int warp = tid >> 5;

    const int bn = blockIdx.x;   // N block (8)
    const int bm = blockIdx.y;   // M block (8)
    const int bz = blockIdx.z;   // batch (64)

    const int* Abase = A    + ((size_t)bz * MDIM + (size_t)bm * BM) * KDIM;
    const int* Bbase = Bmat + ((size_t)bz * NDIM + (size_t)bn * BN) * KDIM;

    // ---- Load int32 tiles, pack to s8x4, stage in smem ----
    #pragma unroll
    for (int i = 0; i < 16; i++) {
        int idx = tid + i * 256;
        int row = idx >> 5;          // 0..127
        int col = idx & 31;          // 0..31 (word within row)
        int4 va = *(const int4*)(Abase + row * KDIM + col * 4);
        uint32_t pa = (uint32_t)(va.x & 0xFF)
                    | ((uint32_t)(va.y & 0xFF) << 8)
                    | ((uint32_t)(va.z & 0xFF) << 16)
                    | ((uint32_t)(va.w & 0xFF) << 24);
        As[row * ROWSTRIDE + col] = pa;

        int4 vb = *(const int4*)(Bbase + row * KDIM + col * 4);
        uint32_t pb = (uint32_t)(vb.x & 0xFF)
                    | ((uint32_t)(vb.y & 0xFF) << 8)
                    | ((uint32_t)(vb.z & 0xFF) << 16)
                    | ((uint32_t)(vb.w & 0xFF) << 24);
        Bs[row * ROWSTRIDE + col] = pb;
    }
    __syncthreads();

    // ---- Warp tiling: 2 x 4 warps, each warp 64(M) x 32(N) ----
    const int warp_m = warp & 1;
    const int warp_n = warp >> 1;

    int acc[4][4][4];
    #pragma unroll
    for (int mi = 0; mi < 4; mi++)
        #pragma unroll
        for (int ni = 0; ni < 4; ni++)
            #pragma unroll
            for (int r = 0; r < 4; r++)
                acc[mi][ni][r] = 0;

    const int lq = lane >> 2;   // group id (0..7)
    const int lr = lane & 3;    // thread-in-group (0..3)

    // ================= IMMA phase: k-words 0..23 =================
    #pragma unroll
    for (int ks = 0; ks < K_MMA_STEPS; ks++) {
        uint32_t af[4][4];
        #pragma unroll
        for (int mi = 0; mi < 4; mi++) {
            int r = warp_m * 64 + mi * 16 + lq;
            const uint32_t* p  = &As[r * ROWSTRIDE + ks * 8 + lr];
            af[mi][0] = p[0];                     // (row g,   k 0..15)
            af[mi][2] = p[4];                     // (row g,   k 16..31)
            const uint32_t* p8 = p + 8 * ROWSTRIDE;
            af[mi][1] = p8[0];                    // (row g+8, k 0..15)
            af[mi][3] = p8[4];                    // (row g+8, k 16..31)
        }
        uint32_t bf[4][2];
        #pragma unroll
        for (int ni = 0; ni < 4; ni++) {
            int c = warp_n * 32 + ni * 8 + lq;
            const uint32_t* p = &Bs[c * ROWSTRIDE + ks * 8 + lr];
            bf[ni][0] = p[0];
            bf[ni][1] = p[4];
        }
        #pragma unroll
        for (int mi = 0; mi < 4; mi++) {
            #pragma unroll
            for (int ni = 0; ni < 4; ni++) {
                asm volatile(
                    "mma.sync.aligned.m16n8k32.row.col.s32.s8.s8.s32 "
                    "{%0,%1,%2,%3}, {%4,%5,%6,%7}, {%8,%9}, {%0,%1,%2,%3};"
                    : "+r"(acc[mi][ni][0]), "+r"(acc[mi][ni][1]),
                      "+r"(acc[mi][ni][2]), "+r"(acc[mi][ni][3])
                    : "r"(af[mi][0]), "r"(af[mi][1]), "r"(af[mi][2]), "r"(af[mi][3]),
                      "r"(bf[ni][0]), "r"(bf[ni][1]));
            }
        }
    }

    // ================= dp4a phase: k-words 24..31 =================
    // Fragment element (mi,ni,r) sits at row = warp_m*64 + mi*16 + lq + (r>=2)*8,
    // col = warp_n*32 + ni*8 + lr*2 + (r&1). Accumulate the remaining K there.
    #pragma unroll
    for (int ch = 0; ch < 4; ch++) {
        const int kw = KW_DP4A + ch * 2;
        uint2 aw[8];
        #pragma unroll
        for (int mi = 0; mi < 4; mi++) {
            #pragma unroll
            for (int h = 0; h < 2; h++) {
                int row = warp_m * 64 + mi * 16 + lq + h * 8;
                aw[mi * 2 + h] = *(const uint2*)&As[row * ROWSTRIDE + kw];
            }
        }
        #pragma unroll
        for (int ni = 0; ni < 4; ni++) {
            #pragma unroll
            for (int d = 0; d < 2; d++) {
                int col = warp_n * 32 + ni * 8 + lr * 2 + d;
                uint2 bw = *(const uint2*)&Bs[col * ROWSTRIDE + kw];
                #pragma unroll
                for (int mi = 0; mi < 4; mi++) {
                    #pragma unroll
                    for (int h = 0; h < 2; h++) {
                        int r = h * 2 + d;
                        int v = acc[mi][ni][r];
                        v = __dp4a((int)aw[mi * 2 + h].x, (int)bw.x, v);
                        v = __dp4a((int)aw[mi * 2 + h].y, (int)bw.y, v);
                        acc[mi][ni][r] = v;
                    }
                }
            }
        }
    }

    // ---- Epilogue: round(alpha * acc) through fp16, store as f32 ----
    const float alpha = *alpha_p;
    float* obase = Out + ((size_t)bz * MDIM + (size_t)bm * BM) * NDIM + (size_t)bn * BN;

    #pragma unroll
    for (int mi = 0; mi < 4; mi++) {
        #pragma unroll
        for (int ni = 0; ni < 4; ni++) {
            int r0 = warp_m * 64 + mi * 16 + lq;
            int c0 = warp_n * 32 + ni * 8 + lr * 2;
            float2 v0;
            v0.x = __half2float(__float2half_rn(alpha * (float)acc[mi][ni][0]));
            v0.y = __half2float(__float2half_rn(alpha * (float)acc[mi][ni][1]));
            *(float2*)(obase + (size_t)r0 * NDIM + c0) = v0;
            float2 v1;
            v1.x = __half2float(__float2half_rn(alpha * (float)acc[mi][ni][2]));
            v1.y = __half2float(__float2half_rn(alpha * (float)acc[mi][ni][3]));
            *(float2*)(obase + (size_t)(r0 + 8) * NDIM + c0) = v1;
        }
    }
}

extern "C" void kernel_launch(void* const* d_in, const int* in_sizes, int n_in,
                              void* d_out, int out_size) {
    // alpha is the size-1 input; the two large tensors are a then b in index order.
    int ai = -1, bi = -1, si = -1;
    for (int i = 0; i < n_in; i++) {
        if (in_sizes[i] == 1) { si = i; }
        else if (ai < 0)      { ai = i; }
        else                  { bi = i; }
    }
    const int*   a     = (const int*)d_in[ai];
    const int*   b     = (const int*)d_in[bi];
    const float* alpha = (const float*)d_in[si];
    float*       out   = (float*)d_out;

    dim3 grid(NDIM / BN, MDIM / BM, BATCH);   // (8, 8, 64)
    dim3 block(256);
    bmm_s8_hybrid_kernel<<<grid, block>>>(a, b, alpha, out);
}